// round 16
// baseline (speedup 1.0000x reference)
#include <cuda_runtime.h>
#include <cuda_bf16.h>
#include <cuda_fp16.h>
#include <math.h>

#define HH 127
#define WW 127
#define CIN 64
#define CI  16
#define STR 4
#define OHW 31
#define LL  961           // 31*31
#define DD  784           // 16*49
#define BB  4
#define TOPM 100
#define LP 1024           // padded L
#define KP 832            // padded K (row stride of bf16 buffers)
#define NST 25            // 25 k-stages of 32 cover 800 >= 784
#define SP 964            // score row pitch (16B-aligned rows)

#define OPB 10240         // one operand tile in smem: 128 rows * 80B
#define STAGE_B (4*OPB)   // Ah, Al, Bh, Bl

// ---------------- scratch (device globals; no allocation allowed) ------------
__device__ float d_b1[BB*CI*HH*WW];
__device__ float d_b2[BB*CI*HH*WW];
__device__ float d_b3[BB*CI*HH*WW];
__device__ __nv_bfloat16 d_p1h[BB*LP*KP];
__device__ __nv_bfloat16 d_p1l[BB*LP*KP];
__device__ __nv_bfloat16 d_p2h[BB*LP*KP];
__device__ __nv_bfloat16 d_p2l[BB*LP*KP];
__device__ __half d_p3h[BB*LL*DD];
__device__ float d_score[BB*LL*SP];
__device__ float d_sall[BB*DD];
__device__ float d_out16[BB*CI*HH*WW];

// ---------------- PTX helpers --------------------------------------------------
__device__ __forceinline__ unsigned smem_u32(const void* p) {
    unsigned a;
    asm("{ .reg .u64 t; cvta.to.shared.u64 t, %1; cvt.u32.u64 %0, t; }" : "=r"(a) : "l"(p));
    return a;
}
__device__ __forceinline__ void cpa16(unsigned sdst, const void* gsrc) {
    asm volatile("cp.async.cg.shared.global [%0], [%1], 16;" :: "r"(sdst), "l"(gsrc));
}
#define CP_COMMIT() asm volatile("cp.async.commit_group;" ::: "memory")
#define CP_WAIT1()  asm volatile("cp.async.wait_group 1;" ::: "memory")

#define LDSM4(R, addr) \
    asm volatile("ldmatrix.sync.aligned.m8n8.x4.shared.b16 {%0,%1,%2,%3}, [%4];" \
        : "=r"((R)[0]),"=r"((R)[1]),"=r"((R)[2]),"=r"((R)[3]) : "r"(addr))

#define MMA16816(D, A, B0, B1) \
    asm volatile("mma.sync.aligned.m16n8k16.row.col.f32.bf16.bf16.f32 " \
        "{%0,%1,%2,%3}, {%4,%5,%6,%7}, {%8,%9}, {%0,%1,%2,%3};" \
        : "+f"((D)[0]),"+f"((D)[1]),"+f"((D)[2]),"+f"((D)[3]) \
        : "r"((A)[0]),"r"((A)[1]),"r"((A)[2]),"r"((A)[3]), "r"(B0),"r"(B1))

// ---------------- zero kernels (3 launches so conv lands in profile slot 4) ----
__global__ void zero_a_kernel() {
    const int n = BB*CI*HH*WW/2;
    for (int i = blockIdx.x*blockDim.x + threadIdx.x; i < n; i += gridDim.x*blockDim.x)
        d_out16[i] = 0.f;
}
__global__ void zero_b_kernel() {
    const int n0 = BB*CI*HH*WW/2, n = BB*CI*HH*WW;
    for (int i = n0 + blockIdx.x*blockDim.x + threadIdx.x; i < n; i += gridDim.x*blockDim.x)
        d_out16[i] = 0.f;
}
__global__ void zero_sall_kernel() {
    int i = blockIdx.x*blockDim.x + threadIdx.x;
    if (i < BB*DD) d_sall[i] = 0.f;
}

// ---------------- fused conv3x3 (g) + conv1x1 (theta, phi) -------------------
// 16x16 tile, 512 threads (16co x 16row x 2colgroups): each thread computes
// 8 pixel columns -> 24 accumulators, ~2x warps/SM vs the 256-thread version.
__global__ void __launch_bounds__(512, 2) conv_kernel(
                            const float* __restrict__ x,
                            const float* __restrict__ g_w,  const float* __restrict__ g_b,
                            const float* __restrict__ th_w, const float* __restrict__ th_b,
                            const float* __restrict__ ph_w, const float* __restrict__ ph_b) {
    __shared__ float  xs[16][18][18];
    __shared__ float4 gw4[16][16][3];   // [co][ci][12 floats padded]
    __shared__ float  tw[16][16];
    __shared__ float  pw[16][16];

    const int b  = blockIdx.z;
    const int h0 = blockIdx.y * 16, w0 = blockIdx.x * 16;
    const int tx = threadIdx.x, ty = threadIdx.y, tz = threadIdx.z;
    const int tid = (tz*16 + ty)*16 + tx;
    const int co = tx, row = ty;
    const int cb = tz * 8;              // column group base (0 or 8)

    float ag[8], at[8], ap[8];
    #pragma unroll
    for (int c = 0; c < 8; c++) { ag[c]=0.f; at[c]=0.f; ap[c]=0.f; }

    const float* xb = x + (size_t)b*CIN*HH*WW;

    for (int c0 = 0; c0 < CIN; c0 += 16) {
        for (int i = tid; i < 16*18*18; i += 512) {
            int cc = i / 324;
            int rr = (i / 18) % 18;
            int col = i % 18;
            int hh = h0 - 1 + rr, ww2 = w0 - 1 + col;
            float v = 0.f;
            if (hh >= 0 && hh < HH && ww2 >= 0 && ww2 < WW)
                v = xb[(size_t)(c0+cc)*HH*WW + hh*WW + ww2];
            xs[cc][rr][col] = v;
        }
        for (int i = tid; i < 16*16*9; i += 512) {
            int o = i / 144, ci = (i / 9) % 16, kk = i % 9;
            ((float*)&gw4[o][ci][0])[kk] = g_w[((o*CIN) + (c0+ci))*9 + kk];
        }
        if (tid < 256) {
            int o = tid / 16, ci = tid % 16;
            tw[o][ci] = th_w[o*CIN + c0 + ci];
            pw[o][ci] = ph_w[o*CIN + c0 + ci];
        }
        __syncthreads();

        for (int ci = 0; ci < 16; ci++) {
            float4 w0v = gw4[co][ci][0];
            float4 w1v = gw4[co][ci][1];
            float4 w2v = gw4[co][ci][2];
            const float wv[9] = { w0v.x, w0v.y, w0v.z, w0v.w,
                                  w1v.x, w1v.y, w1v.z, w1v.w, w2v.x };
            const float tws = tw[co][ci], pws = pw[co][ci];

            #pragma unroll
            for (int ki = 0; ki < 3; ki++) {
                // window cols [cb .. cb+9]: 5 float2 loads (cb even, pitch 18)
                const float2* rp = (const float2*)&xs[ci][row + ki][cb];
                float rv[10];
                #pragma unroll
                for (int j = 0; j < 5; j++) {
                    float2 v2 = rp[j];
                    rv[2*j] = v2.x; rv[2*j + 1] = v2.y;
                }
                #pragma unroll
                for (int c = 0; c < 8; c++) {
                    float s = ag[c];
                    s = fmaf(wv[3*ki+0], rv[c],   s);
                    s = fmaf(wv[3*ki+1], rv[c+1], s);
                    s = fmaf(wv[3*ki+2], rv[c+2], s);
                    ag[c] = s;
                }
                if (ki == 1) {
                    #pragma unroll
                    for (int c = 0; c < 8; c++) {
                        at[c] = fmaf(tws, rv[c+1], at[c]);
                        ap[c] = fmaf(pws, rv[c+1], ap[c]);
                    }
                }
            }
        }
        __syncthreads();
    }

    const int h = h0 + row;
    if (h < HH) {
        const float gb = g_b[co], tb = th_b[co], pb = ph_b[co];
        size_t baseo = ((size_t)(b*CI + co)*HH + h)*WW + w0 + cb;
        #pragma unroll
        for (int c = 0; c < 8; c++) {
            if (w0 + cb + c < WW) {
                d_b1[baseo + c] = ag[c] + gb;
                d_b2[baseo + c] = at[c] + tb;
                d_b3[baseo + c] = ap[c] + pb;
            }
        }
    }
}

// ---------------- unfold + bf16 split + fp16 p3 + zero pads --------------------
__global__ void unfold_kernel() {
    const int total = BB*LP*KP;
    int i = blockIdx.x*blockDim.x + threadIdx.x;
    if (i >= total) return;
    int k = i % KP;
    int l = (i / KP) % LP;
    int b = i / (KP*LP);
    if (l < LL && k < DD) {
        int c = k / 49, rem = k % 49, ki = rem / 7, kj = rem % 7;
        int li = l / OHW, lj = l % OHW;
        int h = li*STR + ki, w = lj*STR + kj;
        size_t src = ((size_t)(b*CI + c)*HH + h)*WW + w;
        float v1 = d_b1[src], v2 = d_b2[src], v3 = d_b3[src];
        __nv_bfloat16 h1 = __float2bfloat16(v1);
        d_p1h[i] = h1;
        d_p1l[i] = __float2bfloat16(v1 - __bfloat162float(h1));
        __nv_bfloat16 h2 = __float2bfloat16(v2);
        d_p2h[i] = h2;
        d_p2l[i] = __float2bfloat16(v2 - __bfloat162float(h2));
        d_p3h[((size_t)b*LL + l)*DD + k] = __float2half_rn(v3);
    } else {
        __nv_bfloat16 z = __float2bfloat16(0.f);
        d_p1h[i] = z; d_p1l[i] = z; d_p2h[i] = z; d_p2l[i] = z;
    }
}

// ---------------- S_all from fp16 p3: split-m with atomics ---------------------
__global__ void sall_kernel() {
    int b = blockIdx.z;
    int d2 = blockIdx.x*blockDim.x + threadIdx.x;   // half2 index
    if (d2 >= DD/2) return;
    int m0 = blockIdx.y * 16;
    int m1 = m0 + 16; if (m1 > LL) m1 = LL;
    const __half2* base = (const __half2*)(d_p3h + (size_t)b*LL*DD) + d2;
    float sx = 0.f, sy = 0.f;
    #pragma unroll 4
    for (int m = m0; m < m1; m++) {
        float2 f = __half22float2(base[(size_t)m*(DD/2)]);
        sx += f.x; sy += f.y;
    }
    atomicAdd(&d_sall[b*DD + 2*d2],     sx);
    atomicAdd(&d_sall[b*DD + 2*d2 + 1], sy);
}

// ---------------- score = P1 @ P2^T: 2-stage BK=32 (R10 champion) --------------
__global__ void __launch_bounds__(256, 2) score_gemm_mma() {
    extern __shared__ char smem[];
    const unsigned sb = smem_u32(smem);
    const int b = blockIdx.z;
    const int tmb = blockIdx.y * 128, tnb = blockIdx.x * 128;
    const int tid = threadIdx.x;
    const int wid = tid >> 5, lane = tid & 31;
    const int warp_m = wid >> 2;
    const int warp_n = wid & 3;

    const char* gops[4] = {
        (const char*)(d_p1h + (size_t)b*LP*KP + (size_t)tmb*KP),
        (const char*)(d_p1l + (size_t)b*LP*KP + (size_t)tmb*KP),
        (const char*)(d_p2h + (size_t)b*LP*KP + (size_t)tnb*KP),
        (const char*)(d_p2l + (size_t)b*LP*KP + (size_t)tnb*KP)
    };

    const unsigned aoff = (unsigned)((warp_m*64 + (lane & 15))*80 + (lane >> 4)*16);
    const unsigned boff = (unsigned)((warp_n*32 + (lane & 7) + ((lane >> 4) << 3))*80
                                     + ((lane >> 3) & 1)*16);

    float acc[4][4][4];
    #pragma unroll
    for (int i = 0; i < 4; i++)
        #pragma unroll
        for (int j = 0; j < 4; j++)
            #pragma unroll
            for (int q = 0; q < 4; q++) acc[i][j][q] = 0.f;

    #define LOAD_STAGE(s) do { \
        unsigned st_ = sb + ((s) & 1)*STAGE_B; \
        _Pragma("unroll") \
        for (int j_ = 0; j_ < 8; j_++) { \
            int idx_ = j_*256 + tid; \
            int op_ = idx_ >> 9, row_ = (idx_ >> 2) & 127, c_ = idx_ & 3; \
            cpa16(st_ + op_*OPB + row_*80 + c_*16, \
                  gops[op_] + (size_t)row_*(KP*2) + (size_t)(s)*64 + c_*16); \
        } \
    } while (0)

    LOAD_STAGE(0); CP_COMMIT();
    LOAD_STAGE(1); CP_COMMIT();

    for (int s = 0; s < NST; s++) {
        CP_WAIT1();
        __syncthreads();
        const unsigned stg = sb + (s & 1)*STAGE_B;

        #pragma unroll
        for (int k16 = 0; k16 < 2; k16++) {
            unsigned bh[8], bl[8];
            const unsigned bbase = stg + 2*OPB + boff + k16*32;
            LDSM4(bh + 0, bbase);
            LDSM4(bh + 4, bbase + 16*80);
            LDSM4(bl + 0, bbase + OPB);
            LDSM4(bl + 4, bbase + OPB + 16*80);

            #pragma unroll
            for (int mt = 0; mt < 4; mt++) {
                unsigned ah[4], al[4];
                const unsigned abase = stg + aoff + mt*(16*80) + k16*32;
                LDSM4(ah, abase);
                LDSM4(al, abase + OPB);
                #pragma unroll
                for (int nt = 0; nt < 4; nt++) {
                    MMA16816(acc[mt][nt], ah, bh[2*nt], bh[2*nt+1]);
                    MMA16816(acc[mt][nt], ah, bl[2*nt], bl[2*nt+1]);
                    MMA16816(acc[mt][nt], al, bh[2*nt], bh[2*nt+1]);
                }
            }
        }
        __syncthreads();
        if (s + 2 < NST) LOAD_STAGE(s + 2);
        CP_COMMIT();
    }

    #pragma unroll
    for (int mt = 0; mt < 4; mt++) {
        const int gm0 = tmb + warp_m*64 + mt*16 + (lane >> 2);
        #pragma unroll
        for (int nt = 0; nt < 4; nt++) {
            const int gn = tnb + warp_n*32 + nt*8 + (lane & 3)*2;
            const float* C = acc[mt][nt];
            if (gn < LL) {
                const bool two = (gn + 1 < LL);
                if (gm0 < LL) {
                    float* r = d_score + ((size_t)b*LL + gm0)*SP + gn;
                    r[0] = C[0];
                    if (two) r[1] = C[1];
                }
                if (gm0 + 8 < LL) {
                    float* r = d_score + ((size_t)b*LL + gm0 + 8)*SP + gn;
                    r[0] = C[2];
                    if (two) r[1] = C[3];
                }
            }
        }
    }
    #undef LOAD_STAGE
}

// ---------------- monotonic float<->key transform -----------------------------
__device__ __forceinline__ unsigned fkey(float f) {
    unsigned u = __float_as_uint(f);
    return u ^ (((int)u >> 31) | 0x80000000u);
}
__device__ __forceinline__ float funkey(unsigned k) {
    unsigned u = (k & 0x80000000u) ? (k ^ 0x80000000u) : ~k;
    return __uint_as_float(u);
}

// ---------------- per-row: 2-pass radix select, softmax, gather, fold ---------
__global__ void __launch_bounds__(256) topk_agg_kernel() {
    __shared__ unsigned keys[LL];
    __shared__ int candId[LL];
    __shared__ int hist[256];
    __shared__ int scn[257];
    __shared__ unsigned swred[8];
    __shared__ unsigned sKey[TOPM];
    __shared__ int sId[TOPM];
    __shared__ float se[TOPM];
    __shared__ float pacc[98*8];
    __shared__ float sZ;
    __shared__ int sDigit, sKneed;
    __shared__ int cg, ce;

    const int l = blockIdx.x, b = blockIdx.y;
    const int tid = threadIdx.x;
    const int wid = tid >> 5, lane = tid & 31;
    const float* row = d_score + ((size_t)b*LL + l)*SP;

    unsigned kmax = 0;
    #pragma unroll
    for (int r = 0; r < 4; r++) {
        int i = tid + r*256;
        if (i < LL) {
            unsigned k = fkey(row[i]);
            keys[i] = k;
            kmax = max(kmax, k);
        }
    }
    #pragma unroll
    for (int off = 16; off > 0; off >>= 1)
        kmax = max(kmax, __shfl_xor_sync(0xffffffffu, kmax, off));
    if (lane == 0) swred[wid] = kmax;
    if (tid == 0) { sKneed = TOPM; cg = 0; ce = 0; }
    __syncthreads();
    if (tid == 0) {
        unsigned mm = swred[0];
        #pragma unroll
        for (int i = 1; i < 8; i++) mm = max(mm, swred[i]);
        swred[0] = mm;
    }
    __syncthreads();
    const float vmax = funkey(swred[0]);
    const float m = fmaxf(0.f, 10.f * vmax);

    int d1 = -1;
    #pragma unroll
    for (int pass = 0; pass < 2; pass++) {
        hist[tid] = 0;
        __syncthreads();
        const int shift = pass ? 16 : 24;
        const int pd1 = pass ? sDigit : -1;
        #pragma unroll
        for (int r = 0; r < 4; r++) {
            int i = tid + r*256;
            int dg = 0x10000;
            if (i < LL) {
                unsigned k = keys[i];
                if (!pass || (int)(k >> 24) == pd1)
                    dg = (int)((k >> shift) & 255);
            }
            unsigned mg = __match_any_sync(0xffffffffu, dg);
            if (lane == __ffs(mg) - 1 && dg != 0x10000)
                atomicAdd(&hist[dg], __popc(mg));
        }
        __syncthreads();
        if (wid == 0) {
            const int top = 255 - lane*8;
            int loc[8];
            int s = 0;
            #pragma unroll
            for (int q = 0; q < 8; q++) { s += hist[top - q]; loc[q] = s; }
            int incl = s;
            #pragma unroll
            for (int off = 1; off < 32; off <<= 1) {
                int n = __shfl_up_sync(0xffffffffu, incl, off);
                if (lane >= off) incl += n;
            }
            const int excl = incl - s;
            #pragma unroll
            for (int q = 0; q < 8; q++) scn[top - q] = loc[q] + excl;
            if (lane == 0) scn[256] = 0;
        }
        __syncthreads();
        int kc = sKneed;
        int ge = scn[tid], gt = scn[tid + 1];
        __syncthreads();
        if (ge >= kc && gt < kc) { sDigit = tid; sKneed = kc - gt; }
        __syncthreads();
        if (!pass) d1 = sDigit;
    }

    const unsigned T16 = ((unsigned)d1 << 8) | (unsigned)sDigit;
    const int kneedF = sKneed;
    const int nGt = TOPM - kneedF;

    #pragma unroll
    for (int r = 0; r < 4; r++) {
        int i = tid + r*256;
        if (i < LL) {
            unsigned k16 = keys[i] >> 16;
            if (k16 > T16) {
                int p = atomicAdd(&cg, 1);
                sKey[p] = keys[i]; sId[p] = i;
            } else if (k16 == T16) {
                int q = atomicAdd(&ce, 1);
                candId[q] = i;
            }
        }
    }
    __syncthreads();

    {
        const int nc = ce;
        for (int t = tid; t < nc; t += 256) {
            const int  myI = candId[t];
            const unsigned mk = keys[myI];
            int rank = 0;
            for (int j = 0; j < nc; j++) {
                unsigned kj = keys[candId[j]];
                rank += (kj > mk) || (kj == mk && j < t);
            }
            if (rank < kneedF) { sKey[nGt + rank] = mk; sId[nGt + rank] = myI; }
        }
    }
    __syncthreads();

    float myE = 0.f;
    if (tid < TOPM) {
        myE = expf(10.f * funkey(sKey[tid]) - m);
        se[tid] = myE;
    }
    float ws = myE;
    #pragma unroll
    for (int off = 16; off > 0; off >>= 1)
        ws += __shfl_xor_sync(0xffffffffu, ws, off);
    if (lane == 0) ((float*)swred)[wid] = ws;
    __syncthreads();
    if (tid == 0) {
        float t = 0.f;
        #pragma unroll
        for (int i = 0; i < 8; i++) t += ((float*)swred)[i];
        sZ = t;
    }
    __syncthreads();
    const float e0   = expf(-m);
    const float Z    = sZ + (float)(LL - TOPM) * e0;
    const float invZ = 1.f / Z;

    float acc[8];
    #pragma unroll
    for (int q = 0; q < 8; q++) acc[q] = 0.f;
    const int chunk = (tid < 98) ? tid : tid - 98;
    const int jh    = (tid < 98) ? 0 : 1;
    if (tid < 196) {
        const __half* P3b = d_p3h + (size_t)b*LL*DD;
        const int j0 = jh * 50;
        #pragma unroll 2
        for (int j = j0; j < j0 + 50; j++) {
            float wj = se[j] - e0;
            uint4 v = *((const uint4*)(P3b + (size_t)sId[j]*DD) + chunk);
            float2 f0 = __half22float2(*(__half2*)&v.x);
            float2 f1 = __half22float2(*(__half2*)&v.y);
            float2 f2 = __half22float2(*(__half2*)&v.z);
            float2 f3 = __half22float2(*(__half2*)&v.w);
            acc[0] += wj*f0.x; acc[1] += wj*f0.y;
            acc[2] += wj*f1.x; acc[3] += wj*f1.y;
            acc[4] += wj*f2.x; acc[5] += wj*f2.y;
            acc[6] += wj*f3.x; acc[7] += wj*f3.y;
        }
        if (jh == 1) {
            #pragma unroll
            for (int q = 0; q < 8; q++) pacc[chunk*8 + q] = acc[q];
        }
    }
    __syncthreads();

    if (tid < 98) {
        const int li = l / OHW, lj = l % OHW;
        const float* sall = d_sall + b*DD;
        #pragma unroll
        for (int q = 0; q < 8; q++) {
            int d = 8*tid + q;
            float val = (sall[d]*e0 + acc[q] + pacc[tid*8 + q]) * invZ;
            int c = d / 49, rem = d % 49, ki = rem / 7, kj = rem % 7;
            int h = li*STR + ki, w = lj*STR + kj;
            atomicAdd(&d_out16[((size_t)(b*CI + c)*HH + h)*WW + w], val);
        }
    }
}

// ---------------- final: divide by analytic mask, restore conv ----------------
__device__ __forceinline__ int cover_count(int h) {
    int lo = h - 6; if (lo < 0) lo = 0;
    int hi = h;     if (hi > 120) hi = 120;
    return (hi >> 2) - ((lo + 3) >> 2) + 1;
}

__global__ void final_kernel(const float* __restrict__ mt_w, const float* __restrict__ mt_b,
                             const float* __restrict__ rs_w, const float* __restrict__ rs_b,
                             float* __restrict__ out) {
    __shared__ float rw[64][16];
    __shared__ float msum[16];
    __shared__ float mb[16];
    __shared__ float rb[64];

    const int tid = threadIdx.x;
    for (int i = tid; i < 1024; i += 256) rw[i/16][i%16] = rs_w[i];
    if (tid < 64) rb[tid] = rs_b[tid];
    if (tid < 16) {
        float s = 0.f;
        for (int c = 0; c < 64; c++) s += mt_w[tid*64 + c];
        msum[tid] = s;
        mb[tid]   = mt_b[tid];
    }
    __syncthreads();

    const int b = blockIdx.y;
    int pix = blockIdx.x*256 + tid;
    if (pix >= HH*WW) return;
    int h = pix / WW, w = pix % WW;
    float cnt = (float)(cover_count(h) * cover_count(w));

    float t[16];
    #pragma unroll
    for (int c = 0; c < 16; c++) {
        float v = d_out16[((size_t)(b*CI + c)*HH + h)*WW + w];
        t[c] = v / (cnt * msum[c] + mb[c] + 1e-8f);
    }
    #pragma unroll
    for (int o = 0; o < 64; o++) {
        float s = rb[o];
        #pragma unroll
        for (int c = 0; c < 16; c++) s += rw[o][c] * t[c];
        out[((size_t)(b*64 + o)*HH + h)*WW + w] = s;
    }
}

// ---------------- launch ------------------------------------------------------
extern "C" void kernel_launch(void* const* d_in, const int* in_sizes, int n_in,
                              void* d_out, int out_size) {
    const float* x    = (const float*)d_in[0];
    const float* g_w  = (const float*)d_in[1];
    const float* g_b  = (const float*)d_in[2];
    const float* th_w = (const float*)d_in[3];
    const float* th_b = (const float*)d_in[4];
    const float* ph_w = (const float*)d_in[5];
    const float* ph_b = (const float*)d_in[6];
    const float* mt_w = (const float*)d_in[7];
    const float* mt_b = (const float*)d_in[8];
    const float* rs_w = (const float*)d_in[9];
    const float* rs_b = (const float*)d_in[10];
    float* out = (float*)d_out;

    const int gemm_smem = 2*STAGE_B;   // 81920
    cudaFuncSetAttribute(score_gemm_mma, cudaFuncAttributeMaxDynamicSharedMemorySize, gemm_smem);

    // 3 zero launches keep conv_kernel in the ncu capture slot (4th launch).
    zero_a_kernel<<<256, 256>>>();
    zero_b_kernel<<<256, 256>>>();
    zero_sall_kernel<<<(BB*DD + 255)/256, 256>>>();
    conv_kernel<<<dim3(8,8,BB), dim3(16,16,2)>>>(x, g_w, g_b, th_w, th_b, ph_w, ph_b);
    {
        int total = BB*LP*KP;
        unfold_kernel<<<(total + 255)/256, 256>>>();
    }
    score_gemm_mma<<<dim3(8, 8, BB), 256, gemm_smem>>>();
    sall_kernel<<<dim3(2, 61, BB), 256>>>();
    topk_agg_kernel<<<dim3(LL, BB), 256>>>();
    final_kernel<<<dim3((HH*WW + 255)/256, BB), 256>>>(mt_w, mt_b, rs_w, rs_b, out);
}

// round 17
// speedup vs baseline: 1.4802x; 1.4802x over previous
#include <cuda_runtime.h>
#include <cuda_bf16.h>
#include <cuda_fp16.h>
#include <math.h>

#define HH 127
#define WW 127
#define CIN 64
#define CI  16
#define STR 4
#define OHW 31
#define LL  961           // 31*31
#define DD  784           // 16*49
#define BB  4
#define TOPM 100
#define LP 1024           // padded L
#define KP 832            // padded K (row stride of bf16 buffers)
#define NST 25            // 25 k-stages of 32 cover 800 >= 784
#define SP 964            // score row pitch (16B-aligned rows)

#define OPB 10240         // one operand tile in smem: 128 rows * 80B
#define STAGE_B (4*OPB)   // Ah, Al, Bh, Bl

#define XS_PITCH 144      // bytes per (row,col) cell: 72 bf16 (64 used + pad)
#define XS_BYTES (18*18*XS_PITCH)   // 46656
#define CONV_SMEM (2*XS_BYTES)      // 93312

// ---------------- scratch (device globals; no allocation allowed) ------------
__device__ float d_b1[BB*CI*HH*WW];
__device__ float d_b2[BB*CI*HH*WW];
__device__ float d_b3[BB*CI*HH*WW];
__device__ __nv_bfloat16 d_p1h[BB*LP*KP];
__device__ __nv_bfloat16 d_p1l[BB*LP*KP];
__device__ __nv_bfloat16 d_p2h[BB*LP*KP];
__device__ __nv_bfloat16 d_p2l[BB*LP*KP];
__device__ __half d_p3h[BB*LL*DD];
__device__ float d_score[BB*LL*SP];
__device__ float d_sall[BB*DD];
__device__ float d_out16[BB*CI*HH*WW];
__device__ unsigned d_wfh[9*4*6*64];   // weight fragments hi (13824 u32)
__device__ unsigned d_wfl[9*4*6*64];   // weight fragments lo

// ---------------- PTX helpers --------------------------------------------------
__device__ __forceinline__ unsigned smem_u32(const void* p) {
    unsigned a;
    asm("{ .reg .u64 t; cvta.to.shared.u64 t, %1; cvt.u32.u64 %0, t; }" : "=r"(a) : "l"(p));
    return a;
}
__device__ __forceinline__ void cpa16(unsigned sdst, const void* gsrc) {
    asm volatile("cp.async.cg.shared.global [%0], [%1], 16;" :: "r"(sdst), "l"(gsrc));
}
#define CP_COMMIT() asm volatile("cp.async.commit_group;" ::: "memory")
#define CP_WAIT1()  asm volatile("cp.async.wait_group 1;" ::: "memory")

#define LDSM4(R, addr) \
    asm volatile("ldmatrix.sync.aligned.m8n8.x4.shared.b16 {%0,%1,%2,%3}, [%4];" \
        : "=r"((R)[0]),"=r"((R)[1]),"=r"((R)[2]),"=r"((R)[3]) : "r"(addr))

#define MMA16816(D, A, B0, B1) \
    asm volatile("mma.sync.aligned.m16n8k16.row.col.f32.bf16.bf16.f32 " \
        "{%0,%1,%2,%3}, {%4,%5,%6,%7}, {%8,%9}, {%0,%1,%2,%3};" \
        : "+f"((D)[0]),"+f"((D)[1]),"+f"((D)[2]),"+f"((D)[3]) \
        : "r"((A)[0]),"r"((A)[1]),"r"((A)[2]),"r"((A)[3]), "r"(B0),"r"(B1))

// ---------------- weight fragment prep (B operand, exact mma layout) -----------
__global__ void wprep_kernel(const float* __restrict__ g_w,
                             const float* __restrict__ th_w,
                             const float* __restrict__ ph_w) {
    int idx = blockIdx.x*256 + threadIdx.x;   // (tap, cf, nf, lane)
    if (idx >= 9*4*6*32) return;
    int lane = idx & 31;
    int t = idx >> 5;            // (tap*4 + cf)*6 + nf
    int nf = t % 6;
    int cf = (t / 6) % 4;
    int tap = t / 24;
    int n = lane >> 2;
    int co = nf*8 + n;

    unsigned outh[2], outl[2];
    #pragma unroll
    for (int r = 0; r < 2; r++) {
        unsigned hh = 0, ll = 0;
        #pragma unroll
        for (int q = 0; q < 2; q++) {
            int kloc = (lane & 3)*2 + r*8 + q;
            int ci = cf*16 + kloc;
            float wv = 0.f;
            if (co < 16) wv = g_w[((co*CIN) + ci)*9 + tap];
            else if (tap == 4) {
                if (co < 32) wv = th_w[(co-16)*CIN + ci];
                else         wv = ph_w[(co-32)*CIN + ci];
            }
            __nv_bfloat16 bh = __float2bfloat16(wv);
            float rest = wv - __bfloat162float(bh);
            __nv_bfloat16 bl = __float2bfloat16(rest);
            hh |= ((unsigned)*(unsigned short*)&bh) << (16*q);
            ll |= ((unsigned)*(unsigned short*)&bl) << (16*q);
        }
        outh[r] = hh; outl[r] = ll;
    }
    int base = t*64 + lane*2;
    d_wfh[base] = outh[0]; d_wfh[base+1] = outh[1];
    d_wfl[base] = outl[0]; d_wfl[base+1] = outl[1];
}

// ---------------- zero kernels -------------------------------------------------
__global__ void zero_a_kernel() {
    const int n = BB*CI*HH*WW;
    for (int i = blockIdx.x*blockDim.x + threadIdx.x; i < n; i += gridDim.x*blockDim.x)
        d_out16[i] = 0.f;
}
__global__ void zero_sall_kernel() {
    int i = blockIdx.x*blockDim.x + threadIdx.x;
    if (i < BB*DD) d_sall[i] = 0.f;
}

// ---------------- conv via implicit-GEMM on tensor cores -----------------------
// grid (8,8,B), 256 threads (8 warps). Tile = 16x16 pixels, warp = 2 pixel rows.
// smem: x tile [18][18][72ci] bf16 hi + lo. A frags via shifted ldmatrix per tap.
__global__ void __launch_bounds__(256, 2) conv_mma_kernel(
        const float* __restrict__ x,
        const float* __restrict__ g_b, const float* __restrict__ th_b,
        const float* __restrict__ ph_b) {
    extern __shared__ char cs[];
    char* xsh = cs;
    char* xsl = cs + XS_BYTES;
    const unsigned sbh = smem_u32(xsh);
    const unsigned sbl = sbh + XS_BYTES;
    const int b = blockIdx.z;
    const int h0 = blockIdx.y*16, w0 = blockIdx.x*16;
    const int tid = threadIdx.x, wid = tid >> 5, lane = tid & 31;
    const float* xb = x + (size_t)b*CIN*HH*WW;

    // stage tile: (ci, rr, col) -> smem [rr][col][ci], bf16 hi/lo split
    for (int i = tid; i < CIN*18*18; i += 256) {
        int ci = i / 324, rem = i % 324;
        int rr = rem / 18, col = rem % 18;
        int hh = h0 - 1 + rr, ww2 = w0 - 1 + col;
        float v = 0.f;
        if (hh >= 0 && hh < HH && ww2 >= 0 && ww2 < WW)
            v = xb[(size_t)ci*HH*WW + hh*WW + ww2];
        __nv_bfloat16 vh = __float2bfloat16(v);
        __nv_bfloat16 vl = __float2bfloat16(v - __bfloat162float(vh));
        int off = (rr*18 + col)*XS_PITCH + ci*2;
        *(__nv_bfloat16*)(xsh + off) = vh;
        *(__nv_bfloat16*)(xsl + off) = vl;
    }
    __syncthreads();

    float acc[2][6][4];
    #pragma unroll
    for (int g = 0; g < 2; g++)
        #pragma unroll
        for (int nf = 0; nf < 6; nf++)
            #pragma unroll
            for (int q = 0; q < 4; q++) acc[g][nf][q] = 0.f;

    const int pr0 = wid*2;
    const unsigned lofs = (unsigned)((lane & 15)*XS_PITCH + (lane >> 4)*16);

    #pragma unroll
    for (int tap = 0; tap < 9; tap++) {
        const int ki = tap/3, kj = tap%3;
        const int nfmax = (tap == 4) ? 6 : 2;
        #pragma unroll
        for (int cf = 0; cf < 4; cf++) {
            const unsigned a0 = (unsigned)(((pr0+ki)*18 + kj)*XS_PITCH + cf*32) + lofs;
            const unsigned a1 = a0 + 18*XS_PITCH;
            unsigned ah0[4], al0[4], ah1[4], al1[4];
            LDSM4(ah0, sbh + a0); LDSM4(al0, sbl + a0);
            LDSM4(ah1, sbh + a1); LDSM4(al1, sbl + a1);
            const unsigned fbase = (unsigned)(((tap*4 + cf)*6)*64 + lane*2);
            for (int nf = 0; nf < nfmax; nf++) {
                uint2 bh = *(const uint2*)&d_wfh[fbase + nf*64];
                uint2 bl = *(const uint2*)&d_wfl[fbase + nf*64];
                MMA16816(acc[0][nf], ah0, bh.x, bh.y);
                MMA16816(acc[1][nf], ah1, bh.x, bh.y);
                MMA16816(acc[0][nf], ah0, bl.x, bl.y);
                MMA16816(acc[1][nf], ah1, bl.x, bl.y);
                MMA16816(acc[0][nf], al0, bh.x, bh.y);
                MMA16816(acc[1][nf], al1, bh.x, bh.y);
            }
        }
    }

    // epilogue: D rows = pixel cols (pcol, pcol+8), D cols = co within nf
    const int pcol = lane >> 2;
    #pragma unroll
    for (int g = 0; g < 2; g++) {
        const int h = h0 + pr0 + g;
        if (h >= HH) continue;
        #pragma unroll
        for (int nf = 0; nf < 6; nf++) {
            const int cog = nf*8 + (lane & 3)*2;
            float* dst; int cb; const float* bias;
            if (cog < 16)      { dst = d_b1; cb = cog;      bias = g_b; }
            else if (cog < 32) { dst = d_b2; cb = cog - 16; bias = th_b; }
            else               { dst = d_b3; cb = cog - 32; bias = ph_b; }
            const float b0 = bias[cb], b1v = bias[cb+1];
            const size_t r0 = ((size_t)(b*CI + cb)*HH + h)*WW;
            const size_t r1 = ((size_t)(b*CI + cb + 1)*HH + h)*WW;
            const int w1 = w0 + pcol, w2 = w0 + pcol + 8;
            if (w1 < WW) {
                dst[r0 + w1] = acc[g][nf][0] + b0;
                dst[r1 + w1] = acc[g][nf][1] + b1v;
            }
            if (w2 < WW) {
                dst[r0 + w2] = acc[g][nf][2] + b0;
                dst[r1 + w2] = acc[g][nf][3] + b1v;
            }
        }
    }
}

// ---------------- unfold + bf16 split + fp16 p3 + zero pads --------------------
__global__ void unfold_kernel() {
    const int total = BB*LP*KP;
    int i = blockIdx.x*blockDim.x + threadIdx.x;
    if (i >= total) return;
    int k = i % KP;
    int l = (i / KP) % LP;
    int b = i / (KP*LP);
    if (l < LL && k < DD) {
        int c = k / 49, rem = k % 49, ki = rem / 7, kj = rem % 7;
        int li = l / OHW, lj = l % OHW;
        int h = li*STR + ki, w = lj*STR + kj;
        size_t src = ((size_t)(b*CI + c)*HH + h)*WW + w;
        float v1 = d_b1[src], v2 = d_b2[src], v3 = d_b3[src];
        __nv_bfloat16 h1 = __float2bfloat16(v1);
        d_p1h[i] = h1;
        d_p1l[i] = __float2bfloat16(v1 - __bfloat162float(h1));
        __nv_bfloat16 h2 = __float2bfloat16(v2);
        d_p2h[i] = h2;
        d_p2l[i] = __float2bfloat16(v2 - __bfloat162float(h2));
        d_p3h[((size_t)b*LL + l)*DD + k] = __float2half_rn(v3);
    } else {
        __nv_bfloat16 z = __float2bfloat16(0.f);
        d_p1h[i] = z; d_p1l[i] = z; d_p2h[i] = z; d_p2l[i] = z;
    }
}

// ---------------- S_all from fp16 p3: split-m with atomics ---------------------
__global__ void sall_kernel() {
    int b = blockIdx.z;
    int d2 = blockIdx.x*blockDim.x + threadIdx.x;   // half2 index
    if (d2 >= DD/2) return;
    int m0 = blockIdx.y * 16;
    int m1 = m0 + 16; if (m1 > LL) m1 = LL;
    const __half2* base = (const __half2*)(d_p3h + (size_t)b*LL*DD) + d2;
    float sx = 0.f, sy = 0.f;
    #pragma unroll 4
    for (int m = m0; m < m1; m++) {
        float2 f = __half22float2(base[(size_t)m*(DD/2)]);
        sx += f.x; sy += f.y;
    }
    atomicAdd(&d_sall[b*DD + 2*d2],     sx);
    atomicAdd(&d_sall[b*DD + 2*d2 + 1], sy);
}

// ---------------- score = P1 @ P2^T: 2-stage BK=32 (R10 champion) --------------
__global__ void __launch_bounds__(256, 2) score_gemm_mma() {
    extern __shared__ char smem[];
    const unsigned sb = smem_u32(smem);
    const int b = blockIdx.z;
    const int tmb = blockIdx.y * 128, tnb = blockIdx.x * 128;
    const int tid = threadIdx.x;
    const int wid = tid >> 5, lane = tid & 31;
    const int warp_m = wid >> 2;
    const int warp_n = wid & 3;

    const char* gops[4] = {
        (const char*)(d_p1h + (size_t)b*LP*KP + (size_t)tmb*KP),
        (const char*)(d_p1l + (size_t)b*LP*KP + (size_t)tmb*KP),
        (const char*)(d_p2h + (size_t)b*LP*KP + (size_t)tnb*KP),
        (const char*)(d_p2l + (size_t)b*LP*KP + (size_t)tnb*KP)
    };

    const unsigned aoff = (unsigned)((warp_m*64 + (lane & 15))*80 + (lane >> 4)*16);
    const unsigned boff = (unsigned)((warp_n*32 + (lane & 7) + ((lane >> 4) << 3))*80
                                     + ((lane >> 3) & 1)*16);

    float acc[4][4][4];
    #pragma unroll
    for (int i = 0; i < 4; i++)
        #pragma unroll
        for (int j = 0; j < 4; j++)
            #pragma unroll
            for (int q = 0; q < 4; q++) acc[i][j][q] = 0.f;

    #define LOAD_STAGE(s) do { \
        unsigned st_ = sb + ((s) & 1)*STAGE_B; \
        _Pragma("unroll") \
        for (int j_ = 0; j_ < 8; j_++) { \
            int idx_ = j_*256 + tid; \
            int op_ = idx_ >> 9, row_ = (idx_ >> 2) & 127, c_ = idx_ & 3; \
            cpa16(st_ + op_*OPB + row_*80 + c_*16, \
                  gops[op_] + (size_t)row_*(KP*2) + (size_t)(s)*64 + c_*16); \
        } \
    } while (0)

    LOAD_STAGE(0); CP_COMMIT();
    LOAD_STAGE(1); CP_COMMIT();

    for (int s = 0; s < NST; s++) {
        CP_WAIT1();
        __syncthreads();
        const unsigned stg = sb + (s & 1)*STAGE_B;

        #pragma unroll
        for (int k16 = 0; k16 < 2; k16++) {
            unsigned bh[8], bl[8];
            const unsigned bbase = stg + 2*OPB + boff + k16*32;
            LDSM4(bh + 0, bbase);
            LDSM4(bh + 4, bbase + 16*80);
            LDSM4(bl + 0, bbase + OPB);
            LDSM4(bl + 4, bbase + OPB + 16*80);

            #pragma unroll
            for (int mt = 0; mt < 4; mt++) {
                unsigned ah[4], al[4];
                const unsigned abase = stg + aoff + mt*(16*80) + k16*32;
                LDSM4(ah, abase);
                LDSM4(al, abase + OPB);
                #pragma unroll
                for (int nt = 0; nt < 4; nt++) {
                    MMA16816(acc[mt][nt], ah, bh[2*nt], bh[2*nt+1]);
                    MMA16816(acc[mt][nt], ah, bl[2*nt], bl[2*nt+1]);
                    MMA16816(acc[mt][nt], al, bh[2*nt], bh[2*nt+1]);
                }
            }
        }
        __syncthreads();
        if (s + 2 < NST) LOAD_STAGE(s + 2);
        CP_COMMIT();
    }

    #pragma unroll
    for (int mt = 0; mt < 4; mt++) {
        const int gm0 = tmb + warp_m*64 + mt*16 + (lane >> 2);
        #pragma unroll
        for (int nt = 0; nt < 4; nt++) {
            const int gn = tnb + warp_n*32 + nt*8 + (lane & 3)*2;
            const float* C = acc[mt][nt];
            if (gn < LL) {
                const bool two = (gn + 1 < LL);
                if (gm0 < LL) {
                    float* r = d_score + ((size_t)b*LL + gm0)*SP + gn;
                    r[0] = C[0];
                    if (two) r[1] = C[1];
                }
                if (gm0 + 8 < LL) {
                    float* r = d_score + ((size_t)b*LL + gm0 + 8)*SP + gn;
                    r[0] = C[2];
                    if (two) r[1] = C[3];
                }
            }
        }
    }
    #undef LOAD_STAGE
}

// ---------------- monotonic float<->key transform -----------------------------
__device__ __forceinline__ unsigned fkey(float f) {
    unsigned u = __float_as_uint(f);
    return u ^ (((int)u >> 31) | 0x80000000u);
}
__device__ __forceinline__ float funkey(unsigned k) {
    unsigned u = (k & 0x80000000u) ? (k ^ 0x80000000u) : ~k;
    return __uint_as_float(u);
}

// ---------------- per-row: 2-pass radix select, softmax, gather, fold ---------
__global__ void __launch_bounds__(256) topk_agg_kernel() {
    __shared__ unsigned keys[LL];
    __shared__ int candId[LL];
    __shared__ int hist[256];
    __shared__ int scn[257];
    __shared__ unsigned swred[8];
    __shared__ unsigned sKey[TOPM];
    __shared__ int sId[TOPM];
    __shared__ float se[TOPM];
    __shared__ float pacc[98*8];
    __shared__ float sZ;
    __shared__ int sDigit, sKneed;
    __shared__ int cg, ce;

    const int l = blockIdx.x, b = blockIdx.y;
    const int tid = threadIdx.x;
    const int wid = tid >> 5, lane = tid & 31;
    const float* row = d_score + ((size_t)b*LL + l)*SP;

    unsigned kmax = 0;
    #pragma unroll
    for (int r = 0; r < 4; r++) {
        int i = tid + r*256;
        if (i < LL) {
            unsigned k = fkey(row[i]);
            keys[i] = k;
            kmax = max(kmax, k);
        }
    }
    #pragma unroll
    for (int off = 16; off > 0; off >>= 1)
        kmax = max(kmax, __shfl_xor_sync(0xffffffffu, kmax, off));
    if (lane == 0) swred[wid] = kmax;
    if (tid == 0) { sKneed = TOPM; cg = 0; ce = 0; }
    __syncthreads();
    if (tid == 0) {
        unsigned mm = swred[0];
        #pragma unroll
        for (int i = 1; i < 8; i++) mm = max(mm, swred[i]);
        swred[0] = mm;
    }
    __syncthreads();
    const float vmax = funkey(swred[0]);
    const float m = fmaxf(0.f, 10.f * vmax);

    int d1 = -1;
    #pragma unroll
    for (int pass = 0; pass < 2; pass++) {
        hist[tid] = 0;
        __syncthreads();
        const int shift = pass ? 16 : 24;
        const int pd1 = pass ? sDigit : -1;
        #pragma unroll
        for (int r = 0; r < 4; r++) {
            int i = tid + r*256;
            int dg = 0x10000;
            if (i < LL) {
                unsigned k = keys[i];
                if (!pass || (int)(k >> 24) == pd1)
                    dg = (int)((k >> shift) & 255);
            }
            unsigned mg = __match_any_sync(0xffffffffu, dg);
            if (lane == __ffs(mg) - 1 && dg != 0x10000)
                atomicAdd(&hist[dg], __popc(mg));
        }
        __syncthreads();
        if (wid == 0) {
            const int top = 255 - lane*8;
            int loc[8];
            int s = 0;
            #pragma unroll
            for (int q = 0; q < 8; q++) { s += hist[top - q]; loc[q] = s; }
            int incl = s;
            #pragma unroll
            for (int off = 1; off < 32; off <<= 1) {
                int n = __shfl_up_sync(0xffffffffu, incl, off);
                if (lane >= off) incl += n;
            }
            const int excl = incl - s;
            #pragma unroll
            for (int q = 0; q < 8; q++) scn[top - q] = loc[q] + excl;
            if (lane == 0) scn[256] = 0;
        }
        __syncthreads();
        int kc = sKneed;
        int ge = scn[tid], gt = scn[tid + 1];
        __syncthreads();
        if (ge >= kc && gt < kc) { sDigit = tid; sKneed = kc - gt; }
        __syncthreads();
        if (!pass) d1 = sDigit;
    }

    const unsigned T16 = ((unsigned)d1 << 8) | (unsigned)sDigit;
    const int kneedF = sKneed;
    const int nGt = TOPM - kneedF;

    #pragma unroll
    for (int r = 0; r < 4; r++) {
        int i = tid + r*256;
        if (i < LL) {
            unsigned k16 = keys[i] >> 16;
            if (k16 > T16) {
                int p = atomicAdd(&cg, 1);
                sKey[p] = keys[i]; sId[p] = i;
            } else if (k16 == T16) {
                int q = atomicAdd(&ce, 1);
                candId[q] = i;
            }
        }
    }
    __syncthreads();

    {
        const int nc = ce;
        for (int t = tid; t < nc; t += 256) {
            const int  myI = candId[t];
            const unsigned mk = keys[myI];
            int rank = 0;
            for (int j = 0; j < nc; j++) {
                unsigned kj = keys[candId[j]];
                rank += (kj > mk) || (kj == mk && j < t);
            }
            if (rank < kneedF) { sKey[nGt + rank] = mk; sId[nGt + rank] = myI; }
        }
    }
    __syncthreads();

    float myE = 0.f;
    if (tid < TOPM) {
        myE = expf(10.f * funkey(sKey[tid]) - m);
        se[tid] = myE;
    }
    float ws = myE;
    #pragma unroll
    for (int off = 16; off > 0; off >>= 1)
        ws += __shfl_xor_sync(0xffffffffu, ws, off);
    if (lane == 0) ((float*)swred)[wid] = ws;
    __syncthreads();
    if (tid == 0) {
        float t = 0.f;
        #pragma unroll
        for (int i = 0; i < 8; i++) t += ((float*)swred)[i];
        sZ = t;
    }
    __syncthreads();
    const float e0   = expf(-m);
    const float Z    = sZ + (float)(LL - TOPM) * e0;
    const float invZ = 1.f / Z;

    float acc[8];
    #pragma unroll
    for (int q = 0; q < 8; q++) acc[q] = 0.f;
    const int chunk = (tid < 98) ? tid : tid - 98;
    const int jh    = (tid < 98) ? 0 : 1;
    if (tid < 196) {
        const __half* P3b = d_p3h + (size_t)b*LL*DD;
        const int j0 = jh * 50;
        #pragma unroll 2
        for (int j = j0; j < j0 + 50; j++) {
            float wj = se[j] - e0;
            uint4 v = *((const uint4*)(P3b + (size_t)sId[j]*DD) + chunk);
            float2 f0 = __half22float2(*(__half2*)&v.x);
            float2 f1 = __half22float2(*(__half2*)&v.y);
            float2 f2 = __half22float2(*(__half2*)&v.z);
            float2 f3 = __half22float2(*(__half2*)&v.w);
            acc[0] += wj*f0.x; acc[1] += wj*f0.y;
            acc[2] += wj*f1.x; acc[3] += wj*f1.y;
            acc[4] += wj*f2.x; acc[5] += wj*f2.y;
            acc[6] += wj*f3.x; acc[7] += wj*f3.y;
        }
        if (jh == 1) {
            #pragma unroll
            for (int q = 0; q < 8; q++) pacc[chunk*8 + q] = acc[q];
        }
    }
    __syncthreads();

    if (tid < 98) {
        const int li = l / OHW, lj = l % OHW;
        const float* sall = d_sall + b*DD;
        #pragma unroll
        for (int q = 0; q < 8; q++) {
            int d = 8*tid + q;
            float val = (sall[d]*e0 + acc[q] + pacc[tid*8 + q]) * invZ;
            int c = d / 49, rem = d % 49, ki = rem / 7, kj = rem % 7;
            int h = li*STR + ki, w = lj*STR + kj;
            atomicAdd(&d_out16[((size_t)(b*CI + c)*HH + h)*WW + w], val);
        }
    }
}

// ---------------- final: divide by analytic mask, restore conv ----------------
__device__ __forceinline__ int cover_count(int h) {
    int lo = h - 6; if (lo < 0) lo = 0;
    int hi = h;     if (hi > 120) hi = 120;
    return (hi >> 2) - ((lo + 3) >> 2) + 1;
}

__global__ void final_kernel(const float* __restrict__ mt_w, const float* __restrict__ mt_b,
                             const float* __restrict__ rs_w, const float* __restrict__ rs_b,
                             float* __restrict__ out) {
    __shared__ float rw[64][16];
    __shared__ float msum[16];
    __shared__ float mb[16];
    __shared__ float rb[64];

    const int tid = threadIdx.x;
    for (int i = tid; i < 1024; i += 256) rw[i/16][i%16] = rs_w[i];
    if (tid < 64) rb[tid] = rs_b[tid];
    if (tid < 16) {
        float s = 0.f;
        for (int c = 0; c < 64; c++) s += mt_w[tid*64 + c];
        msum[tid] = s;
        mb[tid]   = mt_b[tid];
    }
    __syncthreads();

    const int b = blockIdx.y;
    int pix = blockIdx.x*256 + tid;
    if (pix >= HH*WW) return;
    int h = pix / WW, w = pix % WW;
    float cnt = (float)(cover_count(h) * cover_count(w));

    float t[16];
    #pragma unroll
    for (int c = 0; c < 16; c++) {
        float v = d_out16[((size_t)(b*CI + c)*HH + h)*WW + w];
        t[c] = v / (cnt * msum[c] + mb[c] + 1e-8f);
    }
    #pragma unroll
    for (int o = 0; o < 64; o++) {
        float s = rb[o];
        #pragma unroll
        for (int c = 0; c < 16; c++) s += rw[o][c] * t[c];
        out[((size_t)(b*64 + o)*HH + h)*WW + w] = s;
    }
}

// ---------------- launch ------------------------------------------------------
extern "C" void kernel_launch(void* const* d_in, const int* in_sizes, int n_in,
                              void* d_out, int out_size) {
    const float* x    = (const float*)d_in[0];
    const float* g_w  = (const float*)d_in[1];
    const float* g_b  = (const float*)d_in[2];
    const float* th_w = (const float*)d_in[3];
    const float* th_b = (const float*)d_in[4];
    const float* ph_w = (const float*)d_in[5];
    const float* ph_b = (const float*)d_in[6];
    const float* mt_w = (const float*)d_in[7];
    const float* mt_b = (const float*)d_in[8];
    const float* rs_w = (const float*)d_in[9];
    const float* rs_b = (const float*)d_in[10];
    float* out = (float*)d_out;

    const int gemm_smem = 2*STAGE_B;   // 81920
    cudaFuncSetAttribute(score_gemm_mma, cudaFuncAttributeMaxDynamicSharedMemorySize, gemm_smem);
    cudaFuncSetAttribute(conv_mma_kernel, cudaFuncAttributeMaxDynamicSharedMemorySize, CONV_SMEM);

    // conv_mma stays in the ncu capture slot (4th launch).
    wprep_kernel<<<27, 256>>>(g_w, th_w, ph_w);
    zero_a_kernel<<<256, 256>>>();
    zero_sall_kernel<<<(BB*DD + 255)/256, 256>>>();
    conv_mma_kernel<<<dim3(8,8,BB), 256, CONV_SMEM>>>(x, g_b, th_b, ph_b);
    {
        int total = BB*LP*KP;
        unfold_kernel<<<(total + 255)/256, 256>>>();
    }
    score_gemm_mma<<<dim3(8, 8, BB), 256, gemm_smem>>>();
    sall_kernel<<<dim3(2, 61, BB), 256>>>();
    topk_agg_kernel<<<dim3(LL, BB), 256>>>();
    final_kernel<<<dim3((HH*WW + 255)/256, BB), 256>>>(mt_w, mt_b, rs_w, rs_b, out);
}